// round 14
// baseline (speedup 1.0000x reference)
#include <cuda_runtime.h>
#include <math.h>

// ---------------- problem constants ----------------
#define B_    512
#define L_    64
#define DDYN_ 16
#define DSTAT_ 8
#define H_    512
#define C_    1024
#define KTOP_ 16
#define P_    8
#define NB_   50000
#define CAP_  96
#define OVF_  4096
#define TEMP_ 0.2f

// ---------------- device scratch ----------------
__device__ float g_local[B_ * H_];
__device__ float g_query[B_ * H_];
__device__ float g_sim[B_ * C_];
__device__ float g_donor[B_ * H_];
__device__ float g_proto[B_ * H_];
__device__ float g_fused[B_ * H_];
__device__ float g_fused2[B_ * H_];
__device__ int   g_cnt[NB_];
__device__ int   g_slot[NB_ * CAP_];
__device__ int   g_ovf[OVF_];
__device__ int   g_ovf_cnt;

// ---------------- encoder ----------------
__global__ void encode_kernel(const float* __restrict__ seq,
                              const float* __restrict__ mask,
                              const float* __restrict__ stat,
                              const float* __restrict__ W_seq,
                              const float* __restrict__ W_stat,
                              const float* __restrict__ b_enc)
{
    int b = blockIdx.x;
    int tid = threadIdx.x;       // 512 threads
    __shared__ float pooled[DDYN_];
    __shared__ float sv[DSTAT_];
    __shared__ float msum;

    if (tid < DDYN_) {
        float s = 0.f;
        for (int l = 0; l < L_; l++)
            s += seq[(b * L_ + l) * DDYN_ + tid] * mask[b * L_ + l];
        pooled[tid] = s;
    }
    if (tid == 31) {
        float ms = 0.f;
        for (int l = 0; l < L_; l++) ms += mask[b * L_ + l];
        msum = ms;
    }
    if (tid >= 32 && tid < 32 + DSTAT_) sv[tid - 32] = stat[b * DSTAT_ + (tid - 32)];
    __syncthreads();
    if (tid < DDYN_) pooled[tid] = pooled[tid] / fmaxf(msum, 1e-6f);
    __syncthreads();

    float acc = b_enc[tid];
    #pragma unroll
    for (int d = 0; d < DDYN_; d++) acc += pooled[d] * W_seq[d * H_ + tid];
    #pragma unroll
    for (int s = 0; s < DSTAT_; s++) acc += sv[s] * W_stat[s * H_ + tid];
    g_local[b * H_ + tid] = fmaxf(acc, 0.f);
}

// ================= SGEMM: BM=32, BN=64, BK=32, 256 threads, 2x4 microtile ======
// grid (8, 16) = 128 CTAs, 8 warps/CTA. Double-buffered smem, 1 barrier per tile.

template<int EPI>   // 0 = bias, 1 = bias+relu
__global__ __launch_bounds__(256) void gemmA(const float* __restrict__ A, int K,
                      const float* __restrict__ W,
                      const float* __restrict__ bias,
                      float* __restrict__ C)
{
    __shared__ float As[2][32][36];
    __shared__ float Bs[2][32][64];
    int tid = threadIdx.x;                  // 256
    int tx = tid & 15, ty = tid >> 4;       // n-group 0..15, m-group 0..15
    int bm = blockIdx.y * 32, bn = blockIdx.x * 64;
    int am = tid >> 3, ak = (tid & 7) * 4;  // A loader: row am, 1 float4 along k
    int bk = tid >> 4, bn4 = (tid & 15) * 4;

    float acc[2][4] = {};
    float4 pa, pb0, pb1;

    auto fetch = [&](int t) {
        int k0 = t * 32;
        pa  = *(const float4*)&A[(bm + am) * K + k0 + ak];
        pb0 = *(const float4*)&W[(k0 + bk) * H_ + bn + bn4];
        pb1 = *(const float4*)&W[(k0 + bk + 16) * H_ + bn + bn4];
    };
    auto stage = [&](int s) {
        As[s][ak + 0][am] = pa.x; As[s][ak + 1][am] = pa.y;
        As[s][ak + 2][am] = pa.z; As[s][ak + 3][am] = pa.w;
        *(float4*)&Bs[s][bk][bn4]      = pb0;
        *(float4*)&Bs[s][bk + 16][bn4] = pb1;
    };

    int T = K / 32;
    fetch(0); stage(0);
    __syncthreads();
    for (int t = 0; t < T; t++) {
        int s = t & 1;
        if (t + 1 < T) fetch(t + 1);
        #pragma unroll
        for (int kk = 0; kk < 32; kk++) {
            float2 a = *(const float2*)&As[s][kk][ty * 2];
            float4 b = *(const float4*)&Bs[s][kk][tx * 4];
            acc[0][0] += a.x * b.x; acc[0][1] += a.x * b.y;
            acc[0][2] += a.x * b.z; acc[0][3] += a.x * b.w;
            acc[1][0] += a.y * b.x; acc[1][1] += a.y * b.y;
            acc[1][2] += a.y * b.z; acc[1][3] += a.y * b.w;
        }
        if (t + 1 < T) stage(s ^ 1);
        __syncthreads();
    }

    #pragma unroll
    for (int i = 0; i < 2; i++) {
        int b = bm + ty * 2 + i;
        #pragma unroll
        for (int j = 0; j < 4; j++) {
            int n = bn + tx * 4 + j;
            float v = acc[i][j] + bias[n];
            if (EPI == 1) v = fmaxf(v, 0.f);
            C[b * H_ + n] = v;
        }
    }
}

// Fused transfer + gate + fuse, same tiling, dual accumulators.
__global__ __launch_bounds__(256) void gemm_tg(const float* __restrict__ A_local,
                        const float* __restrict__ A_donor,
                        const float* __restrict__ A_proto,
                        const float* __restrict__ W_tr,
                        const float* __restrict__ b_tr,
                        const float* __restrict__ W_gate,
                        const float* __restrict__ b_gate,
                        float* __restrict__ C)
{
    __shared__ float As[2][32][36];
    __shared__ float Bg[2][32][64];
    __shared__ float Bt[2][32][64];
    int tid = threadIdx.x;                  // 256
    int tx = tid & 15, ty = tid >> 4;
    int bm = blockIdx.y * 32, bn = blockIdx.x * 64;
    int am = tid >> 3, ak = (tid & 7) * 4;
    int bk = tid >> 4, bn4 = (tid & 15) * 4;

    float accG[2][4] = {};
    float accT[2][4] = {};
    float4 pa, pg0, pg1, pt0, pt1;

    auto fetch = [&](int t) {
        const float* A = (t < 16) ? A_local : ((t < 32) ? A_donor : A_proto);
        int koff = (t & 15) * 32;
        pa = *(const float4*)&A[(bm + am) * H_ + koff + ak];
        int kg = t * 32;
        pg0 = *(const float4*)&W_gate[(kg + bk) * H_ + bn + bn4];
        pg1 = *(const float4*)&W_gate[(kg + bk + 16) * H_ + bn + bn4];
        if (t >= 16) {
            int kt = (t - 16) * 32;
            pt0 = *(const float4*)&W_tr[(kt + bk) * H_ + bn + bn4];
            pt1 = *(const float4*)&W_tr[(kt + bk + 16) * H_ + bn + bn4];
        }
    };
    auto stage = [&](int s, bool tr) {
        As[s][ak + 0][am] = pa.x; As[s][ak + 1][am] = pa.y;
        As[s][ak + 2][am] = pa.z; As[s][ak + 3][am] = pa.w;
        *(float4*)&Bg[s][bk][bn4]      = pg0;
        *(float4*)&Bg[s][bk + 16][bn4] = pg1;
        if (tr) {
            *(float4*)&Bt[s][bk][bn4]      = pt0;
            *(float4*)&Bt[s][bk + 16][bn4] = pt1;
        }
    };

    fetch(0); stage(0, false);
    __syncthreads();
    for (int t = 0; t < 48; t++) {
        int s = t & 1;
        bool has_tr = (t >= 16);
        if (t + 1 < 48) fetch(t + 1);
        if (has_tr) {
            #pragma unroll
            for (int kk = 0; kk < 32; kk++) {
                float2 a  = *(const float2*)&As[s][kk][ty * 2];
                float4 bg = *(const float4*)&Bg[s][kk][tx * 4];
                float4 bt = *(const float4*)&Bt[s][kk][tx * 4];
                accG[0][0] += a.x * bg.x; accG[0][1] += a.x * bg.y;
                accG[0][2] += a.x * bg.z; accG[0][3] += a.x * bg.w;
                accG[1][0] += a.y * bg.x; accG[1][1] += a.y * bg.y;
                accG[1][2] += a.y * bg.z; accG[1][3] += a.y * bg.w;
                accT[0][0] += a.x * bt.x; accT[0][1] += a.x * bt.y;
                accT[0][2] += a.x * bt.z; accT[0][3] += a.x * bt.w;
                accT[1][0] += a.y * bt.x; accT[1][1] += a.y * bt.y;
                accT[1][2] += a.y * bt.z; accT[1][3] += a.y * bt.w;
            }
        } else {
            #pragma unroll
            for (int kk = 0; kk < 32; kk++) {
                float2 a  = *(const float2*)&As[s][kk][ty * 2];
                float4 bg = *(const float4*)&Bg[s][kk][tx * 4];
                accG[0][0] += a.x * bg.x; accG[0][1] += a.x * bg.y;
                accG[0][2] += a.x * bg.z; accG[0][3] += a.x * bg.w;
                accG[1][0] += a.y * bg.x; accG[1][1] += a.y * bg.y;
                accG[1][2] += a.y * bg.z; accG[1][3] += a.y * bg.w;
            }
        }
        if (t + 1 < 48) stage(s ^ 1, t + 1 >= 16);
        __syncthreads();
    }

    #pragma unroll
    for (int i = 0; i < 2; i++) {
        int b = bm + ty * 2 + i;
        #pragma unroll
        for (int j = 0; j < 4; j++) {
            int n = bn + tx * 4 + j;
            float tr = fmaxf(accT[i][j] + b_tr[n], 0.f);
            float g = 1.f / (1.f + expf(-(accG[i][j] + b_gate[n])));
            C[b * H_ + n] = g * A_local[b * H_ + n] + (1.f - g) * tr;
        }
    }
}

// ---------------- fused l2norm (in place) + prototype attention ----------------
__global__ void l2proto_kernel(const float* __restrict__ protos)
{
    int b = blockIdx.x;
    int tid = threadIdx.x;   // 256
    int warp = tid >> 5, lane = tid & 31;
    __shared__ float q[H_];
    __shared__ float red[8];
    __shared__ float pw[P_];

    float v0 = g_query[b * H_ + tid];
    float v1 = g_query[b * H_ + 256 + tid];
    float s = v0 * v0 + v1 * v1;
    #pragma unroll
    for (int o = 16; o > 0; o >>= 1) s += __shfl_down_sync(0xffffffffu, s, o);
    if (lane == 0) red[warp] = s;
    __syncthreads();
    if (tid == 0) {
        float t = 0.f;
        #pragma unroll
        for (int w = 0; w < 8; w++) t += red[w];
        red[0] = 1.f / fmaxf(sqrtf(t), 1e-12f);
    }
    __syncthreads();
    float inv = red[0];
    v0 *= inv; v1 *= inv;
    g_query[b * H_ + tid] = v0;
    g_query[b * H_ + 256 + tid] = v1;
    q[tid] = v0; q[256 + tid] = v1;
    __syncthreads();

    // prototype attention: warp p handles prototype p
    {
        float dot = 0.f, nrm = 0.f;
        for (int i = lane; i < H_; i += 32) {
            float p = protos[warp * H_ + i];
            dot += p * q[i];
            nrm += p * p;
        }
        #pragma unroll
        for (int o = 16; o > 0; o >>= 1) {
            dot += __shfl_down_sync(0xffffffffu, dot, o);
            nrm += __shfl_down_sync(0xffffffffu, nrm, o);
        }
        if (lane == 0) pw[warp] = dot / fmaxf(sqrtf(nrm), 1e-12f);
    }
    __syncthreads();
    if (tid == 0) {
        float m = pw[0];
        #pragma unroll
        for (int p = 1; p < P_; p++) m = fmaxf(m, pw[p]);
        float sum = 0.f;
        #pragma unroll
        for (int p = 0; p < P_; p++) { pw[p] = expf(pw[p] - m); sum += pw[p]; }
        float invs = 1.f / sum;
        #pragma unroll
        for (int p = 0; p < P_; p++) pw[p] *= invs;
    }
    __syncthreads();
    for (int h = tid; h < H_; h += 256) {
        float acc = 0.f;
        #pragma unroll
        for (int p = 0; p < P_; p++) acc += pw[p] * protos[p * H_ + h];
        g_proto[b * H_ + h] = acc;
    }
}

// ============ sim via row-inversion: each bank row read ONCE ============

__global__ void sim_fill_kernel(const int* __restrict__ cand)
{
    int e = blockIdx.x * 256 + threadIdx.x;
    if (e >= B_ * C_) return;
    int idx = cand[e];
    int pos = atomicAdd(&g_cnt[idx], 1);
    if (pos < CAP_) {
        g_slot[idx * CAP_ + pos] = e;
    } else {
        int o = atomicAdd(&g_ovf_cnt, 1);
        if (o < OVF_) g_ovf[o] = e;
    }
}

// one warp per bank row; row loaded once (coalesced), dotted against all
// referencing queries (L2-hot, 1 MB). Self-resets g_cnt for the next replay.
__global__ void sim_rows_kernel(const float* __restrict__ bank_keys)
{
    int gw = (blockIdx.x * blockDim.x + threadIdx.x) >> 5;
    int lane = threadIdx.x & 31;
    if (gw >= NB_) return;

    int n = g_cnt[gw];
    if (n == 0) return;
    if (lane == 0) g_cnt[gw] = 0;
    if (n > CAP_) n = CAP_;

    const float4* row = (const float4*)(bank_keys + (size_t)gw * H_);
    float4 kr[4];
    #pragma unroll
    for (int p = 0; p < 4; p++) kr[p] = row[p * 32 + lane];

    const float4* q4 = (const float4*)g_query;
    int base = gw * CAP_;
    int j = 0;
    for (; j + 2 <= n; j += 2) {
        int e0 = g_slot[base + j];
        int e1 = g_slot[base + j + 1];
        int b0 = e0 >> 10, b1 = e1 >> 10;
        float4 q0[4], q1[4];
        #pragma unroll
        for (int p = 0; p < 4; p++) q0[p] = q4[b0 * 128 + p * 32 + lane];
        #pragma unroll
        for (int p = 0; p < 4; p++) q1[p] = q4[b1 * 128 + p * 32 + lane];
        float a0 = 0.f, a1 = 0.f;
        #pragma unroll
        for (int p = 0; p < 4; p++) {
            a0 += kr[p].x * q0[p].x + kr[p].y * q0[p].y + kr[p].z * q0[p].z + kr[p].w * q0[p].w;
            a1 += kr[p].x * q1[p].x + kr[p].y * q1[p].y + kr[p].z * q1[p].z + kr[p].w * q1[p].w;
        }
        #pragma unroll
        for (int o = 16; o > 0; o >>= 1) {
            a0 += __shfl_xor_sync(0xffffffffu, a0, o);
            a1 += __shfl_xor_sync(0xffffffffu, a1, o);
        }
        if (lane == 0) {
            g_sim[e0] = a0;
            g_sim[e1] = a1;
        }
    }
    if (j < n) {
        int e0 = g_slot[base + j];
        int b0 = e0 >> 10;
        float a0 = 0.f;
        #pragma unroll
        for (int p = 0; p < 4; p++) {
            float4 q0 = q4[b0 * 128 + p * 32 + lane];
            a0 += kr[p].x * q0.x + kr[p].y * q0.y + kr[p].z * q0.z + kr[p].w * q0.w;
        }
        #pragma unroll
        for (int o = 16; o > 0; o >>= 1)
            a0 += __shfl_xor_sync(0xffffffffu, a0, o);
        if (lane == 0) g_sim[e0] = a0;
    }
}

// overflow fixup: processes the (normally empty) overflow list, resets counter.
__global__ void sim_fixup_kernel(const float* __restrict__ bank_keys,
                                 const int* __restrict__ cand)
{
    __shared__ int n;
    if (threadIdx.x == 0) n = g_ovf_cnt;
    __syncthreads();
    int nn = n; if (nn > OVF_) nn = OVF_;
    for (int i = threadIdx.x; i < nn; i += 256) {
        int e = g_ovf[i];
        int b = e >> 10;
        int idx = cand[e];
        const float* row = bank_keys + (size_t)idx * H_;
        const float* q = g_query + b * H_;
        float acc = 0.f;
        for (int h = 0; h < H_; h++) acc += row[h] * q[h];
        g_sim[e] = acc;
    }
    __syncthreads();
    if (threadIdx.x == 0) g_ovf_cnt = 0;
}

// ---------------- top-16 + softmax + donor gather ----------------
__global__ void topk_donor_kernel(const int* __restrict__ cand,
                                  const float* __restrict__ bank_values)
{
    int b = blockIdx.x;
    int tid = threadIdx.x;   // 256
    int warp = tid >> 5, lane = tid & 31;
    __shared__ float s[C_];
    __shared__ float wv[8];
    __shared__ int   wi[8];
    __shared__ float topv[KTOP_];
    __shared__ float topw[KTOP_];
    __shared__ int   topg[KTOP_];

    for (int i = tid; i < C_; i += 256) s[i] = g_sim[b * C_ + i];
    __syncthreads();

    for (int it = 0; it < KTOP_; it++) {
        float bv = -1e30f; int bi = 0x7fffffff;
        #pragma unroll
        for (int r = 0; r < C_ / 256; r++) {
            int i = tid + r * 256;
            float v = s[i];
            if (v > bv || (v == bv && i < bi)) { bv = v; bi = i; }
        }
        #pragma unroll
        for (int o = 16; o > 0; o >>= 1) {
            float ov = __shfl_down_sync(0xffffffffu, bv, o);
            int   oi = __shfl_down_sync(0xffffffffu, bi, o);
            if (ov > bv || (ov == bv && oi < bi)) { bv = ov; bi = oi; }
        }
        if (lane == 0) { wv[warp] = bv; wi[warp] = bi; }
        __syncthreads();
        if (tid == 0) {
            float mv = wv[0]; int mi = wi[0];
            #pragma unroll
            for (int w = 1; w < 8; w++) {
                if (wv[w] > mv || (wv[w] == mv && wi[w] < mi)) { mv = wv[w]; mi = wi[w]; }
            }
            topv[it] = mv;
            topg[it] = cand[b * C_ + mi];
            s[mi] = -1e30f;
        }
        __syncthreads();
    }

    if (tid == 0) {
        float m = topv[0];
        float sum = 0.f;
        #pragma unroll
        for (int k = 0; k < KTOP_; k++) {
            float e = expf((topv[k] - m) / TEMP_);
            topw[k] = e; sum += e;
        }
        float inv = 1.f / sum;
        #pragma unroll
        for (int k = 0; k < KTOP_; k++) topw[k] *= inv;
    }
    __syncthreads();

    for (int h = tid; h < H_; h += 256) {
        float acc = 0.f;
        #pragma unroll
        for (int k = 0; k < KTOP_; k++)
            acc += topw[k] * bank_values[(size_t)topg[k] * H_ + h];
        g_donor[b * H_ + h] = acc;
    }
}

// ---------------- heads ----------------
__global__ void heads_kernel(const float* __restrict__ W_quant,
                             const float* __restrict__ b_quant,
                             const float* __restrict__ W_ev,
                             const float* __restrict__ b_ev,
                             float* __restrict__ out)
{
    int b = blockIdx.x;
    int tid = threadIdx.x;   // 256, 8 warps -> 8 outputs
    int warp = tid >> 5, lane = tid & 31;
    __shared__ float res[8];
    const float* x = g_fused2 + b * H_;

    float acc = 0.f;
    if (warp < 6) {
        int t = warp / 3, q = warp % 3;
        for (int h = lane; h < H_; h += 32)
            acc += x[h] * W_quant[(t * H_ + h) * 3 + q];
        #pragma unroll
        for (int o = 16; o > 0; o >>= 1) acc += __shfl_down_sync(0xffffffffu, acc, o);
        if (lane == 0) res[warp] = acc + b_quant[t * 3 + q];
    } else {
        int t = warp - 6;
        for (int h = lane; h < H_; h += 32)
            acc += x[h] * W_ev[t * H_ + h];
        #pragma unroll
        for (int o = 16; o > 0; o >>= 1) acc += __shfl_down_sync(0xffffffffu, acc, o);
        if (lane == 0) res[warp] = acc + b_ev[t];
    }
    __syncthreads();
    if (tid == 0) {
        #pragma unroll
        for (int t = 0; t < 2; t++) {
            float a = res[t * 3 + 0], c = res[t * 3 + 1], d = res[t * 3 + 2];
            float tmp;
            if (a > c) { tmp = a; a = c; c = tmp; }
            if (c > d) { tmp = c; c = d; d = tmp; }
            if (a > c) { tmp = a; a = c; c = tmp; }
            out[b * 8 + t * 3 + 0] = a;
            out[b * 8 + t * 3 + 1] = c;
            out[b * 8 + t * 3 + 2] = d;
        }
        out[b * 8 + 6] = res[6];
        out[b * 8 + 7] = res[7];
    }
}

// ---------------- launch ----------------
extern "C" void kernel_launch(void* const* d_in, const int* in_sizes, int n_in,
                              void* d_out, int out_size)
{
    const float* seq        = (const float*)d_in[0];
    const float* mask       = (const float*)d_in[1];
    const float* stat       = (const float*)d_in[2];
    const float* bank_keys  = (const float*)d_in[3];
    const float* bank_vals  = (const float*)d_in[4];
    const int*   cand       = (const int*)d_in[5];
    const float* W_seq      = (const float*)d_in[6];
    const float* W_stat     = (const float*)d_in[7];
    const float* b_enc      = (const float*)d_in[8];
    const float* W_q        = (const float*)d_in[9];
    const float* b_q        = (const float*)d_in[10];
    const float* protos     = (const float*)d_in[11];
    const float* W_tr       = (const float*)d_in[12];
    const float* b_tr       = (const float*)d_in[13];
    const float* W_gate     = (const float*)d_in[14];
    const float* b_gate     = (const float*)d_in[15];
    const float* W_out      = (const float*)d_in[16];
    const float* b_out      = (const float*)d_in[17];
    const float* W_quant    = (const float*)d_in[18];
    const float* b_quant    = (const float*)d_in[19];
    const float* W_ev       = (const float*)d_in[20];
    const float* b_ev       = (const float*)d_in[21];
    float* out = (float*)d_out;
    (void)in_sizes; (void)n_in; (void)out_size;

    static float *p_local = nullptr, *p_query = nullptr, *p_donor = nullptr,
                 *p_proto = nullptr, *p_fused = nullptr, *p_fused2 = nullptr;
    if (!p_local) {
        cudaGetSymbolAddress((void**)&p_local,  g_local);
        cudaGetSymbolAddress((void**)&p_query,  g_query);
        cudaGetSymbolAddress((void**)&p_donor,  g_donor);
        cudaGetSymbolAddress((void**)&p_proto,  g_proto);
        cudaGetSymbolAddress((void**)&p_fused,  g_fused);
        cudaGetSymbolAddress((void**)&p_fused2, g_fused2);
    }

    dim3 ggrid(H_ / 64, B_ / 32);   // (8, 16) = 128 CTAs, 256 threads each

    // binning for sim (g_cnt self-reset by previous replay's sim_rows)
    sim_fill_kernel<<<(B_ * C_) / 256, 256>>>(cand);

    // encoder + query
    encode_kernel<<<B_, 512>>>(seq, mask, stat, W_seq, W_stat, b_enc);
    gemmA<0><<<ggrid, 256>>>(p_local, H_, W_q, b_q, p_query);

    // normalize query + prototype attention (fused)
    l2proto_kernel<<<B_, 256>>>(protos);

    // similarities: one pass over bank rows + tiny overflow fixup
    sim_rows_kernel<<<(NB_ * 32 + 255) / 256, 256>>>(bank_keys);
    sim_fixup_kernel<<<1, 256>>>(bank_keys, cand);

    // top-16 + donor
    topk_donor_kernel<<<B_, 256>>>(cand, bank_vals);

    // fused transfer+gate+fuse, output projection, heads
    gemm_tg<<<ggrid, 256>>>(p_local, p_donor, p_proto,
                            W_tr, b_tr, W_gate, b_gate, p_fused);
    gemmA<1><<<ggrid, 256>>>(p_fused, H_, W_out, b_out, p_fused2);
    heads_kernel<<<B_, 256>>>(W_quant, b_quant, W_ev, b_ev, out);
}

// round 15
// speedup vs baseline: 1.0016x; 1.0016x over previous
#include <cuda_runtime.h>
#include <math.h>

// ---------------- problem constants ----------------
#define B_    512
#define L_    64
#define DDYN_ 16
#define DSTAT_ 8
#define H_    512
#define C_    1024
#define KTOP_ 16
#define P_    8
#define NB_   50000
#define CAP_  96
#define OVF_  4096
#define TEMP_ 0.2f

// ---------------- device scratch ----------------
__device__ float g_local[B_ * H_];
__device__ float g_query[B_ * H_];
__device__ float g_sim[B_ * C_];
__device__ float g_donor[B_ * H_];
__device__ float g_proto[B_ * H_];
__device__ float g_fused[B_ * H_];
__device__ float g_fused2[B_ * H_];
__device__ int   g_cnt[NB_];
__device__ int   g_slot[NB_ * CAP_];
__device__ int   g_ovf[OVF_];
__device__ int   g_ovf_cnt;

// ---------------- encoder ----------------
__global__ void encode_kernel(const float* __restrict__ seq,
                              const float* __restrict__ mask,
                              const float* __restrict__ stat,
                              const float* __restrict__ W_seq,
                              const float* __restrict__ W_stat,
                              const float* __restrict__ b_enc)
{
    int b = blockIdx.x;
    int tid = threadIdx.x;       // 512 threads
    __shared__ float pooled[DDYN_];
    __shared__ float sv[DSTAT_];
    __shared__ float msum;

    if (tid < DDYN_) {
        float s = 0.f;
        for (int l = 0; l < L_; l++)
            s += seq[(b * L_ + l) * DDYN_ + tid] * mask[b * L_ + l];
        pooled[tid] = s;
    }
    if (tid == 31) {
        float ms = 0.f;
        for (int l = 0; l < L_; l++) ms += mask[b * L_ + l];
        msum = ms;
    }
    if (tid >= 32 && tid < 32 + DSTAT_) sv[tid - 32] = stat[b * DSTAT_ + (tid - 32)];
    __syncthreads();
    if (tid < DDYN_) pooled[tid] = pooled[tid] / fmaxf(msum, 1e-6f);
    __syncthreads();

    float acc = b_enc[tid];
    #pragma unroll
    for (int d = 0; d < DDYN_; d++) acc += pooled[d] * W_seq[d * H_ + tid];
    #pragma unroll
    for (int s = 0; s < DSTAT_; s++) acc += sv[s] * W_stat[s * H_ + tid];
    g_local[b * H_ + tid] = fmaxf(acc, 0.f);
}

// ================= SGEMM: BM=32, BN=64, BK=32, 256 threads, 2x4 microtile ======
// grid (8, 16) = 128 CTAs, 8 warps/CTA. Double-buffered smem, 1 barrier per tile.

template<int EPI>   // 0 = bias, 1 = bias+relu
__global__ __launch_bounds__(256) void gemmA(const float* __restrict__ A, int K,
                      const float* __restrict__ W,
                      const float* __restrict__ bias,
                      float* __restrict__ C)
{
    __shared__ float As[2][32][36];
    __shared__ float Bs[2][32][64];
    int tid = threadIdx.x;                  // 256
    int tx = tid & 15, ty = tid >> 4;       // n-group 0..15, m-group 0..15
    int bm = blockIdx.y * 32, bn = blockIdx.x * 64;
    int am = tid >> 3, ak = (tid & 7) * 4;  // A loader: row am, 1 float4 along k
    int bk = tid >> 4, bn4 = (tid & 15) * 4;

    float acc[2][4] = {};
    float4 pa, pb0, pb1;

    auto fetch = [&](int t) {
        int k0 = t * 32;
        pa  = *(const float4*)&A[(bm + am) * K + k0 + ak];
        pb0 = *(const float4*)&W[(k0 + bk) * H_ + bn + bn4];
        pb1 = *(const float4*)&W[(k0 + bk + 16) * H_ + bn + bn4];
    };
    auto stage = [&](int s) {
        As[s][ak + 0][am] = pa.x; As[s][ak + 1][am] = pa.y;
        As[s][ak + 2][am] = pa.z; As[s][ak + 3][am] = pa.w;
        *(float4*)&Bs[s][bk][bn4]      = pb0;
        *(float4*)&Bs[s][bk + 16][bn4] = pb1;
    };

    int T = K / 32;
    fetch(0); stage(0);
    __syncthreads();
    for (int t = 0; t < T; t++) {
        int s = t & 1;
        if (t + 1 < T) fetch(t + 1);
        #pragma unroll
        for (int kk = 0; kk < 32; kk++) {
            float2 a = *(const float2*)&As[s][kk][ty * 2];
            float4 b = *(const float4*)&Bs[s][kk][tx * 4];
            acc[0][0] += a.x * b.x; acc[0][1] += a.x * b.y;
            acc[0][2] += a.x * b.z; acc[0][3] += a.x * b.w;
            acc[1][0] += a.y * b.x; acc[1][1] += a.y * b.y;
            acc[1][2] += a.y * b.z; acc[1][3] += a.y * b.w;
        }
        if (t + 1 < T) stage(s ^ 1);
        __syncthreads();
    }

    #pragma unroll
    for (int i = 0; i < 2; i++) {
        int b = bm + ty * 2 + i;
        #pragma unroll
        for (int j = 0; j < 4; j++) {
            int n = bn + tx * 4 + j;
            float v = acc[i][j] + bias[n];
            if (EPI == 1) v = fmaxf(v, 0.f);
            C[b * H_ + n] = v;
        }
    }
}

// Fused transfer + gate + fuse, same tiling, dual accumulators.
__global__ __launch_bounds__(256) void gemm_tg(const float* __restrict__ A_local,
                        const float* __restrict__ A_donor,
                        const float* __restrict__ A_proto,
                        const float* __restrict__ W_tr,
                        const float* __restrict__ b_tr,
                        const float* __restrict__ W_gate,
                        const float* __restrict__ b_gate,
                        float* __restrict__ C)
{
    __shared__ float As[2][32][36];
    __shared__ float Bg[2][32][64];
    __shared__ float Bt[2][32][64];
    int tid = threadIdx.x;                  // 256
    int tx = tid & 15, ty = tid >> 4;
    int bm = blockIdx.y * 32, bn = blockIdx.x * 64;
    int am = tid >> 3, ak = (tid & 7) * 4;
    int bk = tid >> 4, bn4 = (tid & 15) * 4;

    float accG[2][4] = {};
    float accT[2][4] = {};
    float4 pa, pg0, pg1, pt0, pt1;

    auto fetch = [&](int t) {
        const float* A = (t < 16) ? A_local : ((t < 32) ? A_donor : A_proto);
        int koff = (t & 15) * 32;
        pa = *(const float4*)&A[(bm + am) * H_ + koff + ak];
        int kg = t * 32;
        pg0 = *(const float4*)&W_gate[(kg + bk) * H_ + bn + bn4];
        pg1 = *(const float4*)&W_gate[(kg + bk + 16) * H_ + bn + bn4];
        if (t >= 16) {
            int kt = (t - 16) * 32;
            pt0 = *(const float4*)&W_tr[(kt + bk) * H_ + bn + bn4];
            pt1 = *(const float4*)&W_tr[(kt + bk + 16) * H_ + bn + bn4];
        }
    };
    auto stage = [&](int s, bool tr) {
        As[s][ak + 0][am] = pa.x; As[s][ak + 1][am] = pa.y;
        As[s][ak + 2][am] = pa.z; As[s][ak + 3][am] = pa.w;
        *(float4*)&Bg[s][bk][bn4]      = pg0;
        *(float4*)&Bg[s][bk + 16][bn4] = pg1;
        if (tr) {
            *(float4*)&Bt[s][bk][bn4]      = pt0;
            *(float4*)&Bt[s][bk + 16][bn4] = pt1;
        }
    };

    fetch(0); stage(0, false);
    __syncthreads();
    for (int t = 0; t < 48; t++) {
        int s = t & 1;
        bool has_tr = (t >= 16);
        if (t + 1 < 48) fetch(t + 1);
        if (has_tr) {
            #pragma unroll
            for (int kk = 0; kk < 32; kk++) {
                float2 a  = *(const float2*)&As[s][kk][ty * 2];
                float4 bg = *(const float4*)&Bg[s][kk][tx * 4];
                float4 bt = *(const float4*)&Bt[s][kk][tx * 4];
                accG[0][0] += a.x * bg.x; accG[0][1] += a.x * bg.y;
                accG[0][2] += a.x * bg.z; accG[0][3] += a.x * bg.w;
                accG[1][0] += a.y * bg.x; accG[1][1] += a.y * bg.y;
                accG[1][2] += a.y * bg.z; accG[1][3] += a.y * bg.w;
                accT[0][0] += a.x * bt.x; accT[0][1] += a.x * bt.y;
                accT[0][2] += a.x * bt.z; accT[0][3] += a.x * bt.w;
                accT[1][0] += a.y * bt.x; accT[1][1] += a.y * bt.y;
                accT[1][2] += a.y * bt.z; accT[1][3] += a.y * bt.w;
            }
        } else {
            #pragma unroll
            for (int kk = 0; kk < 32; kk++) {
                float2 a  = *(const float2*)&As[s][kk][ty * 2];
                float4 bg = *(const float4*)&Bg[s][kk][tx * 4];
                accG[0][0] += a.x * bg.x; accG[0][1] += a.x * bg.y;
                accG[0][2] += a.x * bg.z; accG[0][3] += a.x * bg.w;
                accG[1][0] += a.y * bg.x; accG[1][1] += a.y * bg.y;
                accG[1][2] += a.y * bg.z; accG[1][3] += a.y * bg.w;
            }
        }
        if (t + 1 < 48) stage(s ^ 1, t + 1 >= 16);
        __syncthreads();
    }

    #pragma unroll
    for (int i = 0; i < 2; i++) {
        int b = bm + ty * 2 + i;
        #pragma unroll
        for (int j = 0; j < 4; j++) {
            int n = bn + tx * 4 + j;
            float tr = fmaxf(accT[i][j] + b_tr[n], 0.f);
            float g = 1.f / (1.f + expf(-(accG[i][j] + b_gate[n])));
            C[b * H_ + n] = g * A_local[b * H_ + n] + (1.f - g) * tr;
        }
    }
}

// ---------------- fused l2norm (in place) + prototype attention ----------------
__global__ void l2proto_kernel(const float* __restrict__ protos)
{
    int b = blockIdx.x;
    int tid = threadIdx.x;   // 256
    int warp = tid >> 5, lane = tid & 31;
    __shared__ float q[H_];
    __shared__ float red[8];
    __shared__ float pw[P_];

    float v0 = g_query[b * H_ + tid];
    float v1 = g_query[b * H_ + 256 + tid];
    float s = v0 * v0 + v1 * v1;
    #pragma unroll
    for (int o = 16; o > 0; o >>= 1) s += __shfl_down_sync(0xffffffffu, s, o);
    if (lane == 0) red[warp] = s;
    __syncthreads();
    if (tid == 0) {
        float t = 0.f;
        #pragma unroll
        for (int w = 0; w < 8; w++) t += red[w];
        red[0] = 1.f / fmaxf(sqrtf(t), 1e-12f);
    }
    __syncthreads();
    float inv = red[0];
    v0 *= inv; v1 *= inv;
    g_query[b * H_ + tid] = v0;
    g_query[b * H_ + 256 + tid] = v1;
    q[tid] = v0; q[256 + tid] = v1;
    __syncthreads();

    // prototype attention: warp p handles prototype p
    {
        float dot = 0.f, nrm = 0.f;
        for (int i = lane; i < H_; i += 32) {
            float p = protos[warp * H_ + i];
            dot += p * q[i];
            nrm += p * p;
        }
        #pragma unroll
        for (int o = 16; o > 0; o >>= 1) {
            dot += __shfl_down_sync(0xffffffffu, dot, o);
            nrm += __shfl_down_sync(0xffffffffu, nrm, o);
        }
        if (lane == 0) pw[warp] = dot / fmaxf(sqrtf(nrm), 1e-12f);
    }
    __syncthreads();
    if (tid == 0) {
        float m = pw[0];
        #pragma unroll
        for (int p = 1; p < P_; p++) m = fmaxf(m, pw[p]);
        float sum = 0.f;
        #pragma unroll
        for (int p = 0; p < P_; p++) { pw[p] = expf(pw[p] - m); sum += pw[p]; }
        float invs = 1.f / sum;
        #pragma unroll
        for (int p = 0; p < P_; p++) pw[p] *= invs;
    }
    __syncthreads();
    for (int h = tid; h < H_; h += 256) {
        float acc = 0.f;
        #pragma unroll
        for (int p = 0; p < P_; p++) acc += pw[p] * protos[p * H_ + h];
        g_proto[b * H_ + h] = acc;
    }
}

// ============ sim via row-inversion: each bank row read ONCE ============

__global__ void sim_fill_kernel(const int* __restrict__ cand)
{
    int e = blockIdx.x * 256 + threadIdx.x;
    if (e >= B_ * C_) return;
    int idx = cand[e];
    int pos = atomicAdd(&g_cnt[idx], 1);
    if (pos < CAP_) {
        g_slot[idx * CAP_ + pos] = e;
    } else {
        int o = atomicAdd(&g_ovf_cnt, 1);
        if (o < OVF_) g_ovf[o] = e;
    }
}

// one warp per bank row; row loaded once (coalesced), dotted against all
// referencing queries (L2-hot, 1 MB). Self-resets g_cnt for the next replay.
__global__ void sim_rows_kernel(const float* __restrict__ bank_keys)
{
    int gw = (blockIdx.x * blockDim.x + threadIdx.x) >> 5;
    int lane = threadIdx.x & 31;
    if (gw >= NB_) return;

    int n = g_cnt[gw];
    if (n == 0) return;
    if (lane == 0) g_cnt[gw] = 0;
    if (n > CAP_) n = CAP_;

    const float4* row = (const float4*)(bank_keys + (size_t)gw * H_);
    float4 kr[4];
    #pragma unroll
    for (int p = 0; p < 4; p++) kr[p] = row[p * 32 + lane];

    const float4* q4 = (const float4*)g_query;
    int base = gw * CAP_;
    int j = 0;
    for (; j + 2 <= n; j += 2) {
        int e0 = g_slot[base + j];
        int e1 = g_slot[base + j + 1];
        int b0 = e0 >> 10, b1 = e1 >> 10;
        float4 q0[4], q1[4];
        #pragma unroll
        for (int p = 0; p < 4; p++) q0[p] = q4[b0 * 128 + p * 32 + lane];
        #pragma unroll
        for (int p = 0; p < 4; p++) q1[p] = q4[b1 * 128 + p * 32 + lane];
        float a0 = 0.f, a1 = 0.f;
        #pragma unroll
        for (int p = 0; p < 4; p++) {
            a0 += kr[p].x * q0[p].x + kr[p].y * q0[p].y + kr[p].z * q0[p].z + kr[p].w * q0[p].w;
            a1 += kr[p].x * q1[p].x + kr[p].y * q1[p].y + kr[p].z * q1[p].z + kr[p].w * q1[p].w;
        }
        #pragma unroll
        for (int o = 16; o > 0; o >>= 1) {
            a0 += __shfl_xor_sync(0xffffffffu, a0, o);
            a1 += __shfl_xor_sync(0xffffffffu, a1, o);
        }
        if (lane == 0) {
            g_sim[e0] = a0;
            g_sim[e1] = a1;
        }
    }
    if (j < n) {
        int e0 = g_slot[base + j];
        int b0 = e0 >> 10;
        float a0 = 0.f;
        #pragma unroll
        for (int p = 0; p < 4; p++) {
            float4 q0 = q4[b0 * 128 + p * 32 + lane];
            a0 += kr[p].x * q0.x + kr[p].y * q0.y + kr[p].z * q0.z + kr[p].w * q0.w;
        }
        #pragma unroll
        for (int o = 16; o > 0; o >>= 1)
            a0 += __shfl_xor_sync(0xffffffffu, a0, o);
        if (lane == 0) g_sim[e0] = a0;
    }
}

// overflow fixup: processes the (normally empty) overflow list, resets counter.
__global__ void sim_fixup_kernel(const float* __restrict__ bank_keys,
                                 const int* __restrict__ cand)
{
    __shared__ int n;
    if (threadIdx.x == 0) n = g_ovf_cnt;
    __syncthreads();
    int nn = n; if (nn > OVF_) nn = OVF_;
    for (int i = threadIdx.x; i < nn; i += 256) {
        int e = g_ovf[i];
        int b = e >> 10;
        int idx = cand[e];
        const float* row = bank_keys + (size_t)idx * H_;
        const float* q = g_query + b * H_;
        float acc = 0.f;
        for (int h = 0; h < H_; h++) acc += row[h] * q[h];
        g_sim[e] = acc;
    }
    __syncthreads();
    if (threadIdx.x == 0) g_ovf_cnt = 0;
}

// ---------------- top-16 + softmax + donor gather ----------------
__global__ void topk_donor_kernel(const int* __restrict__ cand,
                                  const float* __restrict__ bank_values)
{
    int b = blockIdx.x;
    int tid = threadIdx.x;   // 256
    int warp = tid >> 5, lane = tid & 31;
    __shared__ float s[C_];
    __shared__ float wv[8];
    __shared__ int   wi[8];
    __shared__ float topv[KTOP_];
    __shared__ float topw[KTOP_];
    __shared__ int   topg[KTOP_];

    for (int i = tid; i < C_; i += 256) s[i] = g_sim[b * C_ + i];
    __syncthreads();

    for (int it = 0; it < KTOP_; it++) {
        float bv = -1e30f; int bi = 0x7fffffff;
        #pragma unroll
        for (int r = 0; r < C_ / 256; r++) {
            int i = tid + r * 256;
            float v = s[i];
            if (v > bv || (v == bv && i < bi)) { bv = v; bi = i; }
        }
        #pragma unroll
        for (int o = 16; o > 0; o >>= 1) {
            float ov = __shfl_down_sync(0xffffffffu, bv, o);
            int   oi = __shfl_down_sync(0xffffffffu, bi, o);
            if (ov > bv || (ov == bv && oi < bi)) { bv = ov; bi = oi; }
        }
        if (lane == 0) { wv[warp] = bv; wi[warp] = bi; }
        __syncthreads();
        if (tid == 0) {
            float mv = wv[0]; int mi = wi[0];
            #pragma unroll
            for (int w = 1; w < 8; w++) {
                if (wv[w] > mv || (wv[w] == mv && wi[w] < mi)) { mv = wv[w]; mi = wi[w]; }
            }
            topv[it] = mv;
            topg[it] = cand[b * C_ + mi];
            s[mi] = -1e30f;
        }
        __syncthreads();
    }

    if (tid == 0) {
        float m = topv[0];
        float sum = 0.f;
        #pragma unroll
        for (int k = 0; k < KTOP_; k++) {
            float e = expf((topv[k] - m) / TEMP_);
            topw[k] = e; sum += e;
        }
        float inv = 1.f / sum;
        #pragma unroll
        for (int k = 0; k < KTOP_; k++) topw[k] *= inv;
    }
    __syncthreads();

    for (int h = tid; h < H_; h += 256) {
        float acc = 0.f;
        #pragma unroll
        for (int k = 0; k < KTOP_; k++)
            acc += topw[k] * bank_values[(size_t)topg[k] * H_ + h];
        g_donor[b * H_ + h] = acc;
    }
}

// ---------------- heads ----------------
__global__ void heads_kernel(const float* __restrict__ W_quant,
                             const float* __restrict__ b_quant,
                             const float* __restrict__ W_ev,
                             const float* __restrict__ b_ev,
                             float* __restrict__ out)
{
    int b = blockIdx.x;
    int tid = threadIdx.x;   // 256, 8 warps -> 8 outputs
    int warp = tid >> 5, lane = tid & 31;
    __shared__ float res[8];
    const float* x = g_fused2 + b * H_;

    float acc = 0.f;
    if (warp < 6) {
        int t = warp / 3, q = warp % 3;
        for (int h = lane; h < H_; h += 32)
            acc += x[h] * W_quant[(t * H_ + h) * 3 + q];
        #pragma unroll
        for (int o = 16; o > 0; o >>= 1) acc += __shfl_down_sync(0xffffffffu, acc, o);
        if (lane == 0) res[warp] = acc + b_quant[t * 3 + q];
    } else {
        int t = warp - 6;
        for (int h = lane; h < H_; h += 32)
            acc += x[h] * W_ev[t * H_ + h];
        #pragma unroll
        for (int o = 16; o > 0; o >>= 1) acc += __shfl_down_sync(0xffffffffu, acc, o);
        if (lane == 0) res[warp] = acc + b_ev[t];
    }
    __syncthreads();
    if (tid == 0) {
        #pragma unroll
        for (int t = 0; t < 2; t++) {
            float a = res[t * 3 + 0], c = res[t * 3 + 1], d = res[t * 3 + 2];
            float tmp;
            if (a > c) { tmp = a; a = c; c = tmp; }
            if (c > d) { tmp = c; c = d; d = tmp; }
            if (a > c) { tmp = a; a = c; c = tmp; }
            out[b * 8 + t * 3 + 0] = a;
            out[b * 8 + t * 3 + 1] = c;
            out[b * 8 + t * 3 + 2] = d;
        }
        out[b * 8 + 6] = res[6];
        out[b * 8 + 7] = res[7];
    }
}

// ---------------- launch ----------------
extern "C" void kernel_launch(void* const* d_in, const int* in_sizes, int n_in,
                              void* d_out, int out_size)
{
    const float* seq        = (const float*)d_in[0];
    const float* mask       = (const float*)d_in[1];
    const float* stat       = (const float*)d_in[2];
    const float* bank_keys  = (const float*)d_in[3];
    const float* bank_vals  = (const float*)d_in[4];
    const int*   cand       = (const int*)d_in[5];
    const float* W_seq      = (const float*)d_in[6];
    const float* W_stat     = (const float*)d_in[7];
    const float* b_enc      = (const float*)d_in[8];
    const float* W_q        = (const float*)d_in[9];
    const float* b_q        = (const float*)d_in[10];
    const float* protos     = (const float*)d_in[11];
    const float* W_tr       = (const float*)d_in[12];
    const float* b_tr       = (const float*)d_in[13];
    const float* W_gate     = (const float*)d_in[14];
    const float* b_gate     = (const float*)d_in[15];
    const float* W_out      = (const float*)d_in[16];
    const float* b_out      = (const float*)d_in[17];
    const float* W_quant    = (const float*)d_in[18];
    const float* b_quant    = (const float*)d_in[19];
    const float* W_ev       = (const float*)d_in[20];
    const float* b_ev       = (const float*)d_in[21];
    float* out = (float*)d_out;
    (void)in_sizes; (void)n_in; (void)out_size;

    static float *p_local = nullptr, *p_query = nullptr, *p_donor = nullptr,
                 *p_proto = nullptr, *p_fused = nullptr, *p_fused2 = nullptr;
    if (!p_local) {
        cudaGetSymbolAddress((void**)&p_local,  g_local);
        cudaGetSymbolAddress((void**)&p_query,  g_query);
        cudaGetSymbolAddress((void**)&p_donor,  g_donor);
        cudaGetSymbolAddress((void**)&p_proto,  g_proto);
        cudaGetSymbolAddress((void**)&p_fused,  g_fused);
        cudaGetSymbolAddress((void**)&p_fused2, g_fused2);
    }

    dim3 ggrid(H_ / 64, B_ / 32);   // (8, 16) = 128 CTAs, 256 threads each

    // binning for sim (g_cnt self-reset by previous replay's sim_rows)
    sim_fill_kernel<<<(B_ * C_) / 256, 256>>>(cand);

    // encoder + query
    encode_kernel<<<B_, 512>>>(seq, mask, stat, W_seq, W_stat, b_enc);
    gemmA<0><<<ggrid, 256>>>(p_local, H_, W_q, b_q, p_query);

    // normalize query + prototype attention (fused)
    l2proto_kernel<<<B_, 256>>>(protos);

    // similarities: one pass over bank rows + tiny overflow fixup
    sim_rows_kernel<<<(NB_ * 32 + 255) / 256, 256>>>(bank_keys);
    sim_fixup_kernel<<<1, 256>>>(bank_keys, cand);

    // top-16 + donor
    topk_donor_kernel<<<B_, 256>>>(cand, bank_vals);

    // fused transfer+gate+fuse, output projection, heads
    gemm_tg<<<ggrid, 256>>>(p_local, p_donor, p_proto,
                            W_tr, b_tr, W_gate, b_gate, p_fused);
    gemmA<1><<<ggrid, 256>>>(p_fused, H_, W_out, b_out, p_fused2);
    heads_kernel<<<B_, 256>>>(W_quant, b_quant, W_ev, b_ev, out);
}

// round 16
// speedup vs baseline: 1.1239x; 1.1221x over previous
#include <cuda_runtime.h>
#include <math.h>

// ---------------- problem constants ----------------
#define B_    512
#define L_    64
#define DDYN_ 16
#define DSTAT_ 8
#define H_    512
#define C_    1024
#define KTOP_ 16
#define P_    8
#define NB_   50000
#define CAP_  96
#define OVF_  4096
#define TEMP_ 0.2f

// ---------------- device scratch ----------------
__device__ float g_local[B_ * H_];
__device__ float g_query[B_ * H_];     // UNNORMALIZED query
__device__ float g_qinv[B_];           // 1 / max(||q||, eps)
__device__ float g_sim[B_ * C_];       // unnormalized sims
__device__ float g_donor[B_ * H_];
__device__ float g_proto[B_ * H_];
__device__ float g_fused[B_ * H_];
__device__ float g_fused2[B_ * H_];
__device__ int   g_cnt[NB_];
__device__ int   g_slot[NB_ * CAP_];
__device__ int   g_ovf[OVF_];
__device__ int   g_ovf_cnt;

// ---------------- encoder ----------------
__global__ void encode_kernel(const float* __restrict__ seq,
                              const float* __restrict__ mask,
                              const float* __restrict__ stat,
                              const float* __restrict__ W_seq,
                              const float* __restrict__ W_stat,
                              const float* __restrict__ b_enc)
{
    int b = blockIdx.x;
    int tid = threadIdx.x;       // 512 threads
    __shared__ float pooled[DDYN_];
    __shared__ float sv[DSTAT_];
    __shared__ float msum;

    if (tid < DDYN_) {
        float s = 0.f;
        for (int l = 0; l < L_; l++)
            s += seq[(b * L_ + l) * DDYN_ + tid] * mask[b * L_ + l];
        pooled[tid] = s;
    }
    if (tid == 31) {
        float ms = 0.f;
        for (int l = 0; l < L_; l++) ms += mask[b * L_ + l];
        msum = ms;
    }
    if (tid >= 32 && tid < 32 + DSTAT_) sv[tid - 32] = stat[b * DSTAT_ + (tid - 32)];
    __syncthreads();
    if (tid < DDYN_) pooled[tid] = pooled[tid] / fmaxf(msum, 1e-6f);
    __syncthreads();

    float acc = b_enc[tid];
    #pragma unroll
    for (int d = 0; d < DDYN_; d++) acc += pooled[d] * W_seq[d * H_ + tid];
    #pragma unroll
    for (int s = 0; s < DSTAT_; s++) acc += sv[s] * W_stat[s * H_ + tid];
    g_local[b * H_ + tid] = fmaxf(acc, 0.f);
}

// ===== SGEMM: BM=32, BN=64, BK=32, 128 threads, 4x4 microtile, double-buffered =====
// grid (8, 16) = 128 CTAs. One barrier per k-tile.

template<int EPI>   // 0 = bias, 1 = bias+relu
__global__ __launch_bounds__(128) void gemmA(const float* __restrict__ A, int K,
                      const float* __restrict__ W,
                      const float* __restrict__ bias,
                      float* __restrict__ C)
{
    __shared__ float As[2][32][36];
    __shared__ float Bs[2][32][64];
    int tid = threadIdx.x;                  // 128
    int tx = tid & 15, ty = tid >> 4;       // n-group 0..15, m-group 0..7
    int bm = blockIdx.y * 32, bn = blockIdx.x * 64;
    int am = tid >> 2, ak = (tid & 3) * 8;  // A loader: row am, 8 floats along k
    int bk = tid >> 4, bn4 = (tid & 15) * 4; // B loader: 4 rows (bk + p*8)

    float acc[4][4] = {};
    float4 pa0, pa1, pb[4];

    auto fetch = [&](int t) {
        int k0 = t * 32;
        const float* ap = &A[(bm + am) * K + k0 + ak];
        pa0 = *(const float4*)ap;
        pa1 = *(const float4*)(ap + 4);
        #pragma unroll
        for (int p = 0; p < 4; p++)
            pb[p] = *(const float4*)&W[(k0 + bk + p * 8) * H_ + bn + bn4];
    };
    auto stage = [&](int s) {
        As[s][ak + 0][am] = pa0.x; As[s][ak + 1][am] = pa0.y;
        As[s][ak + 2][am] = pa0.z; As[s][ak + 3][am] = pa0.w;
        As[s][ak + 4][am] = pa1.x; As[s][ak + 5][am] = pa1.y;
        As[s][ak + 6][am] = pa1.z; As[s][ak + 7][am] = pa1.w;
        #pragma unroll
        for (int p = 0; p < 4; p++)
            *(float4*)&Bs[s][bk + p * 8][bn4] = pb[p];
    };

    int T = K / 32;
    fetch(0); stage(0);
    __syncthreads();
    for (int t = 0; t < T; t++) {
        int s = t & 1;
        if (t + 1 < T) fetch(t + 1);
        #pragma unroll
        for (int kk = 0; kk < 32; kk++) {
            float4 a = *(const float4*)&As[s][kk][ty * 4];
            float4 b = *(const float4*)&Bs[s][kk][tx * 4];
            float av[4] = {a.x, a.y, a.z, a.w};
            float bv[4] = {b.x, b.y, b.z, b.w};
            #pragma unroll
            for (int i = 0; i < 4; i++)
                #pragma unroll
                for (int j = 0; j < 4; j++)
                    acc[i][j] += av[i] * bv[j];
        }
        if (t + 1 < T) stage(s ^ 1);
        __syncthreads();
    }

    #pragma unroll
    for (int i = 0; i < 4; i++) {
        int b = bm + ty * 4 + i;
        #pragma unroll
        for (int j = 0; j < 4; j++) {
            int n = bn + tx * 4 + j;
            float v = acc[i][j] + bias[n];
            if (EPI == 1) v = fmaxf(v, 0.f);
            C[b * H_ + n] = v;
        }
    }
}

// Fused transfer + gate + fuse, same tiling, dual accumulators, double-buffered.
__global__ __launch_bounds__(128) void gemm_tg(const float* __restrict__ A_local,
                        const float* __restrict__ A_donor,
                        const float* __restrict__ A_proto,
                        const float* __restrict__ W_tr,
                        const float* __restrict__ b_tr,
                        const float* __restrict__ W_gate,
                        const float* __restrict__ b_gate,
                        float* __restrict__ C)
{
    __shared__ float As[2][32][36];
    __shared__ float Bg[2][32][64];
    __shared__ float Bt[2][32][64];
    int tid = threadIdx.x;                  // 128
    int tx = tid & 15, ty = tid >> 4;
    int bm = blockIdx.y * 32, bn = blockIdx.x * 64;
    int am = tid >> 2, ak = (tid & 3) * 8;
    int bk = tid >> 4, bn4 = (tid & 15) * 4;

    float accG[4][4] = {};
    float accT[4][4] = {};
    float4 pa0, pa1, pg[4], pt[4];

    auto fetch = [&](int t) {
        const float* A = (t < 16) ? A_local : ((t < 32) ? A_donor : A_proto);
        int koff = (t & 15) * 32;
        const float* ap = &A[(bm + am) * H_ + koff + ak];
        pa0 = *(const float4*)ap;
        pa1 = *(const float4*)(ap + 4);
        int kg = t * 32;
        #pragma unroll
        for (int p = 0; p < 4; p++)
            pg[p] = *(const float4*)&W_gate[(kg + bk + p * 8) * H_ + bn + bn4];
        if (t >= 16) {
            int kt = (t - 16) * 32;
            #pragma unroll
            for (int p = 0; p < 4; p++)
                pt[p] = *(const float4*)&W_tr[(kt + bk + p * 8) * H_ + bn + bn4];
        }
    };
    auto stage = [&](int s, bool tr) {
        As[s][ak + 0][am] = pa0.x; As[s][ak + 1][am] = pa0.y;
        As[s][ak + 2][am] = pa0.z; As[s][ak + 3][am] = pa0.w;
        As[s][ak + 4][am] = pa1.x; As[s][ak + 5][am] = pa1.y;
        As[s][ak + 6][am] = pa1.z; As[s][ak + 7][am] = pa1.w;
        #pragma unroll
        for (int p = 0; p < 4; p++)
            *(float4*)&Bg[s][bk + p * 8][bn4] = pg[p];
        if (tr) {
            #pragma unroll
            for (int p = 0; p < 4; p++)
                *(float4*)&Bt[s][bk + p * 8][bn4] = pt[p];
        }
    };

    fetch(0); stage(0, false);
    __syncthreads();
    for (int t = 0; t < 48; t++) {
        int s = t & 1;
        bool has_tr = (t >= 16);
        if (t + 1 < 48) fetch(t + 1);
        if (has_tr) {
            #pragma unroll
            for (int kk = 0; kk < 32; kk++) {
                float4 a  = *(const float4*)&As[s][kk][ty * 4];
                float4 bg = *(const float4*)&Bg[s][kk][tx * 4];
                float4 bt = *(const float4*)&Bt[s][kk][tx * 4];
                float av[4] = {a.x, a.y, a.z, a.w};
                float gv[4] = {bg.x, bg.y, bg.z, bg.w};
                float tv[4] = {bt.x, bt.y, bt.z, bt.w};
                #pragma unroll
                for (int i = 0; i < 4; i++)
                    #pragma unroll
                    for (int j = 0; j < 4; j++) {
                        accG[i][j] += av[i] * gv[j];
                        accT[i][j] += av[i] * tv[j];
                    }
            }
        } else {
            #pragma unroll
            for (int kk = 0; kk < 32; kk++) {
                float4 a  = *(const float4*)&As[s][kk][ty * 4];
                float4 bg = *(const float4*)&Bg[s][kk][tx * 4];
                float av[4] = {a.x, a.y, a.z, a.w};
                float gv[4] = {bg.x, bg.y, bg.z, bg.w};
                #pragma unroll
                for (int i = 0; i < 4; i++)
                    #pragma unroll
                    for (int j = 0; j < 4; j++)
                        accG[i][j] += av[i] * gv[j];
            }
        }
        if (t + 1 < 48) stage(s ^ 1, t + 1 >= 16);
        __syncthreads();
    }

    #pragma unroll
    for (int i = 0; i < 4; i++) {
        int b = bm + ty * 4 + i;
        #pragma unroll
        for (int j = 0; j < 4; j++) {
            int n = bn + tx * 4 + j;
            float tr = fmaxf(accT[i][j] + b_tr[n], 0.f);
            float g = 1.f / (1.f + expf(-(accG[i][j] + b_gate[n])));
            C[b * H_ + n] = g * A_local[b * H_ + n] + (1.f - g) * tr;
        }
    }
}

// ---------------- prototype attention + query-norm (scale-invariance trick) -------
// q stays UNNORMALIZED everywhere; this kernel computes qinv = 1/max(||q||,eps),
// uses it for the prototype logits, and publishes it for topk's softmax.
__global__ void proto_kernel(const float* __restrict__ protos)
{
    int b = blockIdx.x;
    int tid = threadIdx.x;   // 256
    int warp = tid >> 5, lane = tid & 31;
    __shared__ float q[H_];
    __shared__ float red[8];
    __shared__ float pw[P_];

    float v0 = g_query[b * H_ + tid];
    float v1 = g_query[b * H_ + 256 + tid];
    q[tid] = v0; q[256 + tid] = v1;
    float s = v0 * v0 + v1 * v1;
    #pragma unroll
    for (int o = 16; o > 0; o >>= 1) s += __shfl_down_sync(0xffffffffu, s, o);
    if (lane == 0) red[warp] = s;
    __syncthreads();
    if (tid == 0) {
        float t = 0.f;
        #pragma unroll
        for (int w = 0; w < 8; w++) t += red[w];
        float qi = 1.f / fmaxf(sqrtf(t), 1e-12f);
        red[0] = qi;
        g_qinv[b] = qi;
    }
    __syncthreads();
    float qinv = red[0];

    // warp p handles prototype p: logit = (q . p) * qinv / max(||p||, eps)
    {
        float dot = 0.f, nrm = 0.f;
        for (int i = lane; i < H_; i += 32) {
            float p = protos[warp * H_ + i];
            dot += p * q[i];
            nrm += p * p;
        }
        #pragma unroll
        for (int o = 16; o > 0; o >>= 1) {
            dot += __shfl_down_sync(0xffffffffu, dot, o);
            nrm += __shfl_down_sync(0xffffffffu, nrm, o);
        }
        if (lane == 0) pw[warp] = dot * qinv / fmaxf(sqrtf(nrm), 1e-12f);
    }
    __syncthreads();
    if (tid == 0) {
        float m = pw[0];
        #pragma unroll
        for (int p = 1; p < P_; p++) m = fmaxf(m, pw[p]);
        float sum = 0.f;
        #pragma unroll
        for (int p = 0; p < P_; p++) { pw[p] = expf(pw[p] - m); sum += pw[p]; }
        float invs = 1.f / sum;
        #pragma unroll
        for (int p = 0; p < P_; p++) pw[p] *= invs;
    }
    __syncthreads();
    for (int h = tid; h < H_; h += 256) {
        float acc = 0.f;
        #pragma unroll
        for (int p = 0; p < P_; p++) acc += pw[p] * protos[p * H_ + h];
        g_proto[b * H_ + h] = acc;
    }
}

// ============ sim via row-inversion: each bank row read ONCE ============

__global__ void sim_fill_kernel(const int* __restrict__ cand)
{
    int e = blockIdx.x * 256 + threadIdx.x;
    if (e >= B_ * C_) return;
    int idx = cand[e];
    int pos = atomicAdd(&g_cnt[idx], 1);
    if (pos < CAP_) {
        g_slot[idx * CAP_ + pos] = e;
    } else {
        int o = atomicAdd(&g_ovf_cnt, 1);
        if (o < OVF_) g_ovf[o] = e;
    }
}

// one warp per bank row; row loaded once (coalesced), dotted against all
// referencing (unnormalized) queries. Self-resets g_cnt for the next replay.
__global__ void sim_rows_kernel(const float* __restrict__ bank_keys)
{
    int gw = (blockIdx.x * blockDim.x + threadIdx.x) >> 5;
    int lane = threadIdx.x & 31;
    if (gw >= NB_) return;

    int n = g_cnt[gw];
    if (n == 0) return;
    if (lane == 0) g_cnt[gw] = 0;
    if (n > CAP_) n = CAP_;

    const float4* row = (const float4*)(bank_keys + (size_t)gw * H_);
    float4 kr[4];
    #pragma unroll
    for (int p = 0; p < 4; p++) kr[p] = row[p * 32 + lane];

    const float4* q4 = (const float4*)g_query;
    int base = gw * CAP_;
    int j = 0;
    for (; j + 2 <= n; j += 2) {
        int e0 = g_slot[base + j];
        int e1 = g_slot[base + j + 1];
        int b0 = e0 >> 10, b1 = e1 >> 10;
        float4 q0[4], q1[4];
        #pragma unroll
        for (int p = 0; p < 4; p++) q0[p] = q4[b0 * 128 + p * 32 + lane];
        #pragma unroll
        for (int p = 0; p < 4; p++) q1[p] = q4[b1 * 128 + p * 32 + lane];
        float a0 = 0.f, a1 = 0.f;
        #pragma unroll
        for (int p = 0; p < 4; p++) {
            a0 += kr[p].x * q0[p].x + kr[p].y * q0[p].y + kr[p].z * q0[p].z + kr[p].w * q0[p].w;
            a1 += kr[p].x * q1[p].x + kr[p].y * q1[p].y + kr[p].z * q1[p].z + kr[p].w * q1[p].w;
        }
        #pragma unroll
        for (int o = 16; o > 0; o >>= 1) {
            a0 += __shfl_xor_sync(0xffffffffu, a0, o);
            a1 += __shfl_xor_sync(0xffffffffu, a1, o);
        }
        if (lane == 0) {
            g_sim[e0] = a0;
            g_sim[e1] = a1;
        }
    }
    if (j < n) {
        int e0 = g_slot[base + j];
        int b0 = e0 >> 10;
        float a0 = 0.f;
        #pragma unroll
        for (int p = 0; p < 4; p++) {
            float4 q0 = q4[b0 * 128 + p * 32 + lane];
            a0 += kr[p].x * q0.x + kr[p].y * q0.y + kr[p].z * q0.z + kr[p].w * q0.w;
        }
        #pragma unroll
        for (int o = 16; o > 0; o >>= 1)
            a0 += __shfl_xor_sync(0xffffffffu, a0, o);
        if (lane == 0) g_sim[e0] = a0;
    }
}

// overflow fixup: processes the (normally empty) overflow list, resets counter.
__global__ void sim_fixup_kernel(const float* __restrict__ bank_keys,
                                 const int* __restrict__ cand)
{
    __shared__ int n;
    if (threadIdx.x == 0) n = g_ovf_cnt;
    __syncthreads();
    int nn = n; if (nn > OVF_) nn = OVF_;
    for (int i = threadIdx.x; i < nn; i += 256) {
        int e = g_ovf[i];
        int b = e >> 10;
        int idx = cand[e];
        const float* row = bank_keys + (size_t)idx * H_;
        const float* q = g_query + b * H_;
        float acc = 0.f;
        for (int h = 0; h < H_; h++) acc += row[h] * q[h];
        g_sim[e] = acc;
    }
    __syncthreads();
    if (threadIdx.x == 0) g_ovf_cnt = 0;
}

// ---------------- top-16 + softmax (with qinv scaling) + donor gather ------------
__global__ void topk_donor_kernel(const int* __restrict__ cand,
                                  const float* __restrict__ bank_values)
{
    int b = blockIdx.x;
    int tid = threadIdx.x;   // 256
    int warp = tid >> 5, lane = tid & 31;
    __shared__ float s[C_];
    __shared__ float wv[8];
    __shared__ int   wi[8];
    __shared__ float topv[KTOP_];
    __shared__ float topw[KTOP_];
    __shared__ int   topg[KTOP_];

    for (int i = tid; i < C_; i += 256) s[i] = g_sim[b * C_ + i];
    __syncthreads();

    for (int it = 0; it < KTOP_; it++) {
        float bv = -1e30f; int bi = 0x7fffffff;
        #pragma unroll
        for (int r = 0; r < C_ / 256; r++) {
            int i = tid + r * 256;
            float v = s[i];
            if (v > bv || (v == bv && i < bi)) { bv = v; bi = i; }
        }
        #pragma unroll
        for (int o = 16; o > 0; o >>= 1) {
            float ov = __shfl_down_sync(0xffffffffu, bv, o);
            int   oi = __shfl_down_sync(0xffffffffu, bi, o);
            if (ov > bv || (ov == bv && oi < bi)) { bv = ov; bi = oi; }
        }
        if (lane == 0) { wv[warp] = bv; wi[warp] = bi; }
        __syncthreads();
        if (tid == 0) {
            float mv = wv[0]; int mi = wi[0];
            #pragma unroll
            for (int w = 1; w < 8; w++) {
                if (wv[w] > mv || (wv[w] == mv && wi[w] < mi)) { mv = wv[w]; mi = wi[w]; }
            }
            topv[it] = mv;
            topg[it] = cand[b * C_ + mi];
            s[mi] = -1e30f;
        }
        __syncthreads();
    }

    if (tid == 0) {
        float qinv = g_qinv[b];
        float m = topv[0];              // max of unnormalized too (qinv > 0)
        float sum = 0.f;
        #pragma unroll
        for (int k = 0; k < KTOP_; k++) {
            float e = expf((topv[k] - m) * qinv / TEMP_);
            topw[k] = e; sum += e;
        }
        float inv = 1.f / sum;
        #pragma unroll
        for (int k = 0; k < KTOP_; k++) topw[k] *= inv;
    }
    __syncthreads();

    for (int h = tid; h < H_; h += 256) {
        float acc = 0.f;
        #pragma unroll
        for (int k = 0; k < KTOP_; k++)
            acc += topw[k] * bank_values[(size_t)topg[k] * H_ + h];
        g_donor[b * H_ + h] = acc;
    }
}

// ---------------- heads ----------------
__global__ void heads_kernel(const float* __restrict__ W_quant,
                             const float* __restrict__ b_quant,
                             const float* __restrict__ W_ev,
                             const float* __restrict__ b_ev,
                             float* __restrict__ out)
{
    int b = blockIdx.x;
    int tid = threadIdx.x;   // 256, 8 warps -> 8 outputs
    int warp = tid >> 5, lane = tid & 31;
    __shared__ float res[8];
    const float* x = g_fused2 + b * H_;

    float acc = 0.f;
    if (warp < 6) {
        int t = warp / 3, q = warp % 3;
        for (int h = lane; h < H_; h += 32)
            acc += x[h] * W_quant[(t * H_ + h) * 3 + q];
        #pragma unroll
        for (int o = 16; o > 0; o >>= 1) acc += __shfl_down_sync(0xffffffffu, acc, o);
        if (lane == 0) res[warp] = acc + b_quant[t * 3 + q];
    } else {
        int t = warp - 6;
        for (int h = lane; h < H_; h += 32)
            acc += x[h] * W_ev[t * H_ + h];
        #pragma unroll
        for (int o = 16; o > 0; o >>= 1) acc += __shfl_down_sync(0xffffffffu, acc, o);
        if (lane == 0) res[warp] = acc + b_ev[t];
    }
    __syncthreads();
    if (tid == 0) {
        #pragma unroll
        for (int t = 0; t < 2; t++) {
            float a = res[t * 3 + 0], c = res[t * 3 + 1], d = res[t * 3 + 2];
            float tmp;
            if (a > c) { tmp = a; a = c; c = tmp; }
            if (c > d) { tmp = c; c = d; d = tmp; }
            if (a > c) { tmp = a; a = c; c = tmp; }
            out[b * 8 + t * 3 + 0] = a;
            out[b * 8 + t * 3 + 1] = c;
            out[b * 8 + t * 3 + 2] = d;
        }
        out[b * 8 + 6] = res[6];
        out[b * 8 + 7] = res[7];
    }
}

// ---------------- launch ----------------
extern "C" void kernel_launch(void* const* d_in, const int* in_sizes, int n_in,
                              void* d_out, int out_size)
{
    const float* seq        = (const float*)d_in[0];
    const float* mask       = (const float*)d_in[1];
    const float* stat       = (const float*)d_in[2];
    const float* bank_keys  = (const float*)d_in[3];
    const float* bank_vals  = (const float*)d_in[4];
    const int*   cand       = (const int*)d_in[5];
    const float* W_seq      = (const float*)d_in[6];
    const float* W_stat     = (const float*)d_in[7];
    const float* b_enc      = (const float*)d_in[8];
    const float* W_q        = (const float*)d_in[9];
    const float* b_q        = (const float*)d_in[10];
    const float* protos     = (const float*)d_in[11];
    const float* W_tr       = (const float*)d_in[12];
    const float* b_tr       = (const float*)d_in[13];
    const float* W_gate     = (const float*)d_in[14];
    const float* b_gate     = (const float*)d_in[15];
    const float* W_out      = (const float*)d_in[16];
    const float* b_out      = (const float*)d_in[17];
    const float* W_quant    = (const float*)d_in[18];
    const float* b_quant    = (const float*)d_in[19];
    const float* W_ev       = (const float*)d_in[20];
    const float* b_ev       = (const float*)d_in[21];
    float* out = (float*)d_out;
    (void)in_sizes; (void)n_in; (void)out_size;

    static float *p_local = nullptr, *p_query = nullptr, *p_donor = nullptr,
                 *p_proto = nullptr, *p_fused = nullptr, *p_fused2 = nullptr;
    if (!p_local) {
        cudaGetSymbolAddress((void**)&p_local,  g_local);
        cudaGetSymbolAddress((void**)&p_query,  g_query);
        cudaGetSymbolAddress((void**)&p_donor,  g_donor);
        cudaGetSymbolAddress((void**)&p_proto,  g_proto);
        cudaGetSymbolAddress((void**)&p_fused,  g_fused);
        cudaGetSymbolAddress((void**)&p_fused2, g_fused2);
    }

    dim3 ggrid(H_ / 64, B_ / 32);   // (8, 16) = 128 CTAs, 128 threads each

    // binning for sim (g_cnt self-reset by previous replay's sim_rows)
    sim_fill_kernel<<<(B_ * C_) / 256, 256>>>(cand);

    // encoder + query (unnormalized)
    encode_kernel<<<B_, 512>>>(seq, mask, stat, W_seq, W_stat, b_enc);
    gemmA<0><<<ggrid, 128>>>(p_local, H_, W_q, b_q, p_query);

    // prototype attention + qinv (normalization folded out via scale invariance)
    proto_kernel<<<B_, 256>>>(protos);

    // similarities: one pass over bank rows + tiny overflow fixup
    sim_rows_kernel<<<(NB_ * 32 + 255) / 256, 256>>>(bank_keys);
    sim_fixup_kernel<<<1, 256>>>(bank_keys, cand);

    // top-16 (qinv-scaled softmax) + donor
    topk_donor_kernel<<<B_, 256>>>(cand, bank_vals);

    // fused transfer+gate+fuse, output projection, heads
    gemm_tg<<<ggrid, 128>>>(p_local, p_donor, p_proto,
                            W_tr, b_tr, W_gate, b_gate, p_fused);
    gemmA<1><<<ggrid, 128>>>(p_fused, H_, W_out, b_out, p_fused2);
    heads_kernel<<<B_, 256>>>(W_quant, b_quant, W_ev, b_ev, out);
}